// round 1
// baseline (speedup 1.0000x reference)
#include <cuda_runtime.h>
#include <math.h>

// Problem constants
#define NN 50000
#define FF 48
#define CC 16          // H*C1 with H=1
#define L1 8

// ---------------- device scratch (no allocations allowed) ----------------
__device__ __align__(16) float g_y[NN * CC];     // x @ W
__device__ __align__(16) float g_agg[NN * CC];   // segment sum (init with self loop)
__device__ float g_deg[NN];
__device__ float g_loss;
__device__ int   g_is64;

// ---------------- dtype detection for edge_index ----------------
// If stored int64 (values < 50000), every odd 32-bit word of the first 1024
// entries is zero. If int32, odd words are random node ids (all-zero prob ~0).
__global__ void k_detect(const unsigned* __restrict__ ew) {
    __shared__ unsigned any;
    if (threadIdx.x == 0) any = 0u;
    __syncthreads();
    unsigned v = 0u;
    for (int i = threadIdx.x; i < 1024; i += blockDim.x) v |= ew[2 * i + 1];
    if (v) atomicOr(&any, 1u);
    __syncthreads();
    if (threadIdx.x == 0) g_is64 = (any == 0u) ? 1 : 0;
}

// ---------------- projection y = x @ W, init agg/deg with self loop ----------------
__global__ void k_proj(const float* __restrict__ x, const float* __restrict__ W, int n) {
    __shared__ float sW[FF * CC];
    for (int i = threadIdx.x; i < FF * CC; i += blockDim.x) sW[i] = W[i];
    __syncthreads();
    int idx = blockIdx.x * blockDim.x + threadIdx.x;
    if (idx == 0) g_loss = 0.0f;
    if (idx >= n * CC) return;
    int node = idx / CC;
    int c    = idx % CC;
    const float* xr = x + node * FF;
    float acc = 0.0f;
#pragma unroll
    for (int k = 0; k < FF; k++) acc = fmaf(xr[k], sW[k * CC + c], acc);
    g_y[idx]   = acc;
    g_agg[idx] = acc;     // self loop contribution (q == 1 for H == 1)
    if (c == 0) g_deg[node] = 1.0f;  // self loop degree
}

// ---------------- edge scatter: agg[dst] += y[src], deg[dst] += 1 ----------------
__device__ __forceinline__ void red4(float* addr, float4 v) {
    asm volatile("red.global.add.v4.f32 [%0], {%1,%2,%3,%4};"
                 :: "l"(addr), "f"(v.x), "f"(v.y), "f"(v.z), "f"(v.w) : "memory");
}

__global__ void k_edge(const void* __restrict__ ei, int E) {
    int e = blockIdx.x * blockDim.x + threadIdx.x;
    if (e >= E) return;
    int src, dst;
    if (g_is64) {
        const long long* p = (const long long*)ei;
        src = (int)p[e];
        dst = (int)p[E + e];
    } else {
        const int* p = (const int*)ei;
        src = p[e];
        dst = p[E + e];
    }
    const float4* yr = (const float4*)&g_y[src * CC];
    float4 a = yr[0], b = yr[1], c = yr[2], d = yr[3];
    float* out = &g_agg[dst * CC];
    red4(out + 0,  a);
    red4(out + 4,  b);
    red4(out + 8,  c);
    red4(out + 12, d);
    atomicAdd(&g_deg[dst], 1.0f);
}

// ---------------- head: mean-agg + bias + relu, MLP, sigmoid, BCE reduce ----------------
__global__ void k_head(const float* __restrict__ bias,
                       const float* __restrict__ l1w,  // [16, 8] row-major
                       const float* __restrict__ l1b,  // [8]
                       const float* __restrict__ ow,   // [8, 1]
                       const float* __restrict__ ob,   // [1]
                       const float* __restrict__ labels,
                       const float* __restrict__ wts,
                       float* __restrict__ pout, int n) {
    __shared__ float sb[CC], sl1w[CC * L1], sl1b[L1], sow[L1], sob;
    if (threadIdx.x < CC) sb[threadIdx.x] = bias[threadIdx.x];
    if (threadIdx.x < CC * L1) sl1w[threadIdx.x] = l1w[threadIdx.x];
    if (threadIdx.x < L1) { sl1b[threadIdx.x] = l1b[threadIdx.x]; sow[threadIdx.x] = ow[threadIdx.x]; }
    if (threadIdx.x == 0) sob = ob[0];
    __syncthreads();

    int i = blockIdx.x * blockDim.x + threadIdx.x;
    float term = 0.0f;
    if (i < n) {
        float invdeg = 1.0f / fmaxf(g_deg[i], 1.0f);
        const float4* ar = (const float4*)&g_agg[i * CC];
        float h[CC];
        float4 v0 = ar[0], v1 = ar[1], v2 = ar[2], v3 = ar[3];
        h[0] = v0.x; h[1] = v0.y; h[2]  = v0.z; h[3]  = v0.w;
        h[4] = v1.x; h[5] = v1.y; h[6]  = v1.z; h[7]  = v1.w;
        h[8] = v2.x; h[9] = v2.y; h[10] = v2.z; h[11] = v2.w;
        h[12] = v3.x; h[13] = v3.y; h[14] = v3.z; h[15] = v3.w;
#pragma unroll
        for (int c = 0; c < CC; c++) h[c] = fmaxf(fmaf(h[c], invdeg, sb[c]), 0.0f);

        float h2[L1];
#pragma unroll
        for (int j = 0; j < L1; j++) {
            float s = sl1b[j];
#pragma unroll
            for (int c = 0; c < CC; c++) s = fmaf(h[c], sl1w[c * L1 + j], s);
            h2[j] = fmaxf(s, 0.0f);
        }
        float z = sob;
#pragma unroll
        for (int j = 0; j < L1; j++) z = fmaf(h2[j], sow[j], z);
        float p = 1.0f / (1.0f + expf(-z));
        pout[i] = p;

        const float eps = 1e-7f;
        float pc = fminf(fmaxf(p, eps), 1.0f - eps);
        float lab = labels[i];
        float bce = -(lab * logf(pc) + (1.0f - lab) * logf(1.0f - pc));
        term = wts[i] * bce;
    }
    // block reduction
#pragma unroll
    for (int off = 16; off > 0; off >>= 1)
        term += __shfl_down_sync(0xFFFFFFFFu, term, off);
    __shared__ float warpsum[8];
    int wid = threadIdx.x >> 5, lid = threadIdx.x & 31;
    if (lid == 0) warpsum[wid] = term;
    __syncthreads();
    if (wid == 0) {
        float s = (lid < (blockDim.x >> 5)) ? warpsum[lid] : 0.0f;
#pragma unroll
        for (int off = 4; off > 0; off >>= 1)
            s += __shfl_down_sync(0xFFFFFFFFu, s, off);
        if (lid == 0) atomicAdd(&g_loss, s);
    }
}

__global__ void k_fin(float* out, int n) {
    out[0] = g_loss / (float)n;
}

// ---------------- launch ----------------
extern "C" void kernel_launch(void* const* d_in, const int* in_sizes, int n_in,
                              void* d_out, int out_size) {
    const float* x      = (const float*)d_in[0];
    const void*  ei     = d_in[1];
    const float* labels = (const float*)d_in[2];
    const float* wts    = (const float*)d_in[3];
    const float* W      = (const float*)d_in[4];
    // d_in[5] = u, d_in[6] = c : unused (softmax over H=1 is identically 1)
    const float* bias   = (const float*)d_in[7];
    const float* l1w    = (const float*)d_in[8];
    const float* l1b    = (const float*)d_in[9];
    const float* ow     = (const float*)d_in[10];
    const float* ob     = (const float*)d_in[11];

    int n = in_sizes[0] / FF;
    int E = in_sizes[1] / 2;

    float* out = (float*)d_out;
    int loss_slot = (out_size == n + 1) ? 1 : 0;
    float* pout = loss_slot ? (out + 1) : out;

    k_detect<<<1, 256>>>((const unsigned*)ei);
    k_proj<<<(n * CC + 255) / 256, 256>>>(x, W, n);
    k_edge<<<(E + 255) / 256, 256>>>(ei, E);
    k_head<<<(n + 255) / 256, 256>>>(bias, l1w, l1b, ow, ob, labels, wts, pout, n);
    if (loss_slot) k_fin<<<1, 1>>>(out, n);
}